// round 5
// baseline (speedup 1.0000x reference)
#include <cuda_runtime.h>
#include <cstddef>

#define NN 50000
#define EE 800000
#define ET 850000   // EE + NN self loops
#define NEG 0.2f

// ---------------- scratch (static __device__, no allocations) ----------------
__device__ __align__(16) float g_hfull[NN * 256];   // h = act @ W (layer 1/2)
__device__ __align__(16) float g_h1act[NN * 256];   // relu(gat1 out + b1)
__device__ __align__(16) float g_h2[NN * 64];       // relu(mean-head gat2 + b2)
__device__ __align__(16) float g_hm[NN * 32];
__device__ __align__(16) float g_hs[NN * 32];
__device__ __align__(16) float g_esrc[NN * 4];
__device__ __align__(16) float g_edst[NN * 4];
__device__ __align__(16) float g_e[ET * 4];
__device__ __align__(16) float g_alpha[ET * 4];
__device__ int g_deg[NN];
__device__ int g_rowptr[NN + 1];
__device__ int g_cursor[NN];
__device__ int g_perm[ET];   // CSR position -> original edge id
__device__ int g_srcp[ET];   // CSR position -> src node
__device__ int g_dstp[ET];   // CSR position -> dst node

__device__ __forceinline__ float lrelu(float v) { return v > 0.f ? v : NEG * v; }

// ---------------- CSR build ----------------
__global__ void k_zero_deg() {
    int i = blockIdx.x * blockDim.x + threadIdx.x;
    if (i < NN) g_deg[i] = 0;
}

__global__ void k_hist(const int* __restrict__ ei) {
    int e = blockIdx.x * blockDim.x + threadIdx.x;
    if (e >= ET) return;
    int d = (e < EE) ? ei[EE + e] : (e - EE);
    atomicAdd(&g_deg[d], 1);
}

__global__ void k_scan() {  // single block, 1024 threads
    __shared__ int s[1024];
    __shared__ int carry;
    int tid = threadIdx.x;
    if (tid == 0) { carry = 0; g_rowptr[0] = 0; }
    __syncthreads();
    for (int base = 0; base < NN; base += 1024) {
        int i = base + tid;
        int v = (i < NN) ? g_deg[i] : 0;
        s[tid] = v;
        __syncthreads();
        for (int off = 1; off < 1024; off <<= 1) {
            int tv = (tid >= off) ? s[tid - off] : 0;
            __syncthreads();
            s[tid] += tv;
            __syncthreads();
        }
        int incl = s[tid];
        int c = carry;
        if (i < NN) {
            g_rowptr[i + 1] = c + incl;
            g_cursor[i] = c + incl - v;   // exclusive prefix
        }
        __syncthreads();
        if (tid == 1023) carry = c + incl;
        __syncthreads();
    }
}

__global__ void k_scatter(const int* __restrict__ ei) {
    int e = blockIdx.x * blockDim.x + threadIdx.x;
    if (e >= ET) return;
    int sN, dN;
    if (e < EE) { sN = ei[e]; dN = ei[EE + e]; }
    else        { sN = dN = e - EE; }
    int pos = atomicAdd(&g_cursor[dN], 1);
    g_perm[pos] = e;
    g_srcp[pos] = sN;
    g_dstp[pos] = dN;
}

// ---------------- SGEMM: C[M,N] = A[M,K] @ B[K,N], 128x128x16, 8x8 micro ----------------
__global__ __launch_bounds__(256) void k_sgemm(const float* __restrict__ A,
                                               const float* __restrict__ B,
                                               float* __restrict__ C,
                                               int M, int N, int K) {
    __shared__ float As[16][128];
    __shared__ float Bs[16][128];
    const int tid = threadIdx.x;
    const int bm = blockIdx.y * 128, bn = blockIdx.x * 128;
    const int aRow = tid >> 2, aCol = (tid & 3) * 4;
    const int bRow = tid >> 5, bCol = (tid & 31) * 4;
    const int tx = tid & 15, ty = tid >> 4;
    float acc[8][8] = {};
    for (int k0 = 0; k0 < K; k0 += 16) {
#pragma unroll
        for (int i = 0; i < 2; i++) {
            int r = aRow + i * 64, gr = bm + r;
            float4 a = (gr < M) ? *(const float4*)(A + (size_t)gr * K + k0 + aCol)
                                : make_float4(0.f, 0.f, 0.f, 0.f);
            As[aCol + 0][r] = a.x; As[aCol + 1][r] = a.y;
            As[aCol + 2][r] = a.z; As[aCol + 3][r] = a.w;
        }
#pragma unroll
        for (int i = 0; i < 2; i++) {
            int r = bRow + i * 8;
            *(float4*)&Bs[r][bCol] = *(const float4*)(B + (size_t)(k0 + r) * N + bn + bCol);
        }
        __syncthreads();
#pragma unroll
        for (int k = 0; k < 16; k++) {
            float4 a0 = *(float4*)&As[k][ty * 8], a1 = *(float4*)&As[k][ty * 8 + 4];
            float4 b0 = *(float4*)&Bs[k][tx * 8], b1 = *(float4*)&Bs[k][tx * 8 + 4];
            float af[8] = {a0.x, a0.y, a0.z, a0.w, a1.x, a1.y, a1.z, a1.w};
            float bf[8] = {b0.x, b0.y, b0.z, b0.w, b1.x, b1.y, b1.z, b1.w};
#pragma unroll
            for (int i = 0; i < 8; i++)
#pragma unroll
                for (int j = 0; j < 8; j++) acc[i][j] += af[i] * bf[j];
        }
        __syncthreads();
    }
#pragma unroll
    for (int i = 0; i < 8; i++) {
        int gr = bm + ty * 8 + i;
        if (gr >= M) continue;
        float* cp = C + (size_t)gr * N + bn + tx * 8;
        *(float4*)cp       = make_float4(acc[i][0], acc[i][1], acc[i][2], acc[i][3]);
        *(float4*)(cp + 4) = make_float4(acc[i][4], acc[i][5], acc[i][6], acc[i][7]);
    }
}

// ---------------- small GEMM: [M,64] @ [64,32] -> [M,32] ----------------
__global__ void k_gemm_small(const float* __restrict__ A, const float* __restrict__ W,
                             float* __restrict__ C, int M) {
    __shared__ float Ws[64 * 32];
    int tid = threadIdx.y * 32 + threadIdx.x;
    for (int i = tid; i < 64 * 32; i += 256) Ws[i] = W[i];
    __syncthreads();
    int row = blockIdx.x * 8 + threadIdx.y;
    if (row >= M) return;
    int col = threadIdx.x;
    const float* a = A + (size_t)row * 64;
    float acc = 0.f;
#pragma unroll 8
    for (int k = 0; k < 64; k++) acc += a[k] * Ws[k * 32 + col];
    C[(size_t)row * 32 + col] = acc;
}

// ---------------- attention coefficients, 256-feature layers (H=4,C=64) ----------------
__global__ void k_coef4(const float* __restrict__ hfull, const float* __restrict__ as_,
                        const float* __restrict__ ad_) {
    int n = blockIdx.x;
    int t = threadIdx.x;
    float v = hfull[(size_t)n * 256 + t];
    float ps = v * as_[t], pd = v * ad_[t];
#pragma unroll
    for (int o = 16; o > 0; o >>= 1) {
        ps += __shfl_down_sync(0xffffffffu, ps, o);
        pd += __shfl_down_sync(0xffffffffu, pd, o);
    }
    __shared__ float ss[8], sd[8];
    if ((t & 31) == 0) { ss[t >> 5] = ps; sd[t >> 5] = pd; }
    __syncthreads();
    if (t < 4) {
        g_esrc[n * 4 + t] = ss[2 * t] + ss[2 * t + 1];
        g_edst[n * 4 + t] = sd[2 * t] + sd[2 * t + 1];
    }
}

// ---------------- attention coefficients, 32-feature heads (H=1) ----------------
__global__ void k_coef1(const float* __restrict__ hf, const float* __restrict__ as_,
                        const float* __restrict__ ad_) {
    int n = blockIdx.x * 8 + (threadIdx.x >> 5);
    if (n >= NN) return;
    int lane = threadIdx.x & 31;
    float v = hf[(size_t)n * 32 + lane];
    float ps = v * as_[lane], pd = v * ad_[lane];
#pragma unroll
    for (int o = 16; o > 0; o >>= 1) {
        ps += __shfl_down_sync(0xffffffffu, ps, o);
        pd += __shfl_down_sync(0xffffffffu, pd, o);
    }
    if (lane == 0) { g_esrc[n] = ps; g_edst[n] = pd; }
}

// ---------------- per-edge logits, CSR order ----------------
__global__ void k_edge4() {
    int j = blockIdx.x * blockDim.x + threadIdx.x;
    if (j >= ET) return;
    int s = g_srcp[j], d = g_dstp[j];
    float4 es = ((const float4*)g_esrc)[s];
    float4 ed = ((const float4*)g_edst)[d];
    float4 r;
    r.x = lrelu(es.x + ed.x); r.y = lrelu(es.y + ed.y);
    r.z = lrelu(es.z + ed.z); r.w = lrelu(es.w + ed.w);
    ((float4*)g_e)[j] = r;
}

__global__ void k_edge1() {
    int j = blockIdx.x * blockDim.x + threadIdx.x;
    if (j >= ET) return;
    g_e[j] = lrelu(g_esrc[g_srcp[j]] + g_edst[g_dstp[j]]);
}

// ---------------- segment softmax (warp per node), H=4 ----------------
__global__ void k_softmax4(float* __restrict__ aw_out) {
    int n = blockIdx.x * 8 + (threadIdx.x >> 5);
    if (n >= NN) return;
    int lane = threadIdx.x & 31;
    int s = g_rowptr[n], t = g_rowptr[n + 1];
    float4 mx = make_float4(-1e30f, -1e30f, -1e30f, -1e30f);
    for (int j = s + lane; j < t; j += 32) {
        float4 v = ((const float4*)g_e)[j];
        mx.x = fmaxf(mx.x, v.x); mx.y = fmaxf(mx.y, v.y);
        mx.z = fmaxf(mx.z, v.z); mx.w = fmaxf(mx.w, v.w);
    }
#pragma unroll
    for (int o = 16; o > 0; o >>= 1) {
        mx.x = fmaxf(mx.x, __shfl_xor_sync(0xffffffffu, mx.x, o));
        mx.y = fmaxf(mx.y, __shfl_xor_sync(0xffffffffu, mx.y, o));
        mx.z = fmaxf(mx.z, __shfl_xor_sync(0xffffffffu, mx.z, o));
        mx.w = fmaxf(mx.w, __shfl_xor_sync(0xffffffffu, mx.w, o));
    }
    float4 sum = make_float4(0.f, 0.f, 0.f, 0.f);
    for (int j = s + lane; j < t; j += 32) {
        float4 v = ((const float4*)g_e)[j];
        v.x = __expf(v.x - mx.x); v.y = __expf(v.y - mx.y);
        v.z = __expf(v.z - mx.z); v.w = __expf(v.w - mx.w);
        ((float4*)g_e)[j] = v;
        sum.x += v.x; sum.y += v.y; sum.z += v.z; sum.w += v.w;
    }
#pragma unroll
    for (int o = 16; o > 0; o >>= 1) {
        sum.x += __shfl_xor_sync(0xffffffffu, sum.x, o);
        sum.y += __shfl_xor_sync(0xffffffffu, sum.y, o);
        sum.z += __shfl_xor_sync(0xffffffffu, sum.z, o);
        sum.w += __shfl_xor_sync(0xffffffffu, sum.w, o);
    }
    float4 inv;
    inv.x = 1.f / (sum.x + 1e-16f); inv.y = 1.f / (sum.y + 1e-16f);
    inv.z = 1.f / (sum.z + 1e-16f); inv.w = 1.f / (sum.w + 1e-16f);
    for (int j = s + lane; j < t; j += 32) {
        float4 v = ((const float4*)g_e)[j];
        float4 a = make_float4(v.x * inv.x, v.y * inv.y, v.z * inv.z, v.w * inv.w);
        ((float4*)g_alpha)[j] = a;
        ((float4*)aw_out)[g_perm[j]] = a;
    }
}

// ---------------- segment softmax, H=1 ----------------
__global__ void k_softmax1(float* __restrict__ aw_out) {
    int n = blockIdx.x * 8 + (threadIdx.x >> 5);
    if (n >= NN) return;
    int lane = threadIdx.x & 31;
    int s = g_rowptr[n], t = g_rowptr[n + 1];
    float mx = -1e30f;
    for (int j = s + lane; j < t; j += 32) mx = fmaxf(mx, g_e[j]);
#pragma unroll
    for (int o = 16; o > 0; o >>= 1) mx = fmaxf(mx, __shfl_xor_sync(0xffffffffu, mx, o));
    float sum = 0.f;
    for (int j = s + lane; j < t; j += 32) {
        float v = __expf(g_e[j] - mx);
        g_e[j] = v;
        sum += v;
    }
#pragma unroll
    for (int o = 16; o > 0; o >>= 1) sum += __shfl_xor_sync(0xffffffffu, sum, o);
    float inv = 1.f / (sum + 1e-16f);
    for (int j = s + lane; j < t; j += 32) {
        float a = g_e[j] * inv;
        g_alpha[j] = a;
        aw_out[g_perm[j]] = a;
    }
}

// ---------------- aggregation, 256-feature layers. block(256) per node ----------------
// concat=1: out[n,256] = relu(sum + bias)          (layer 1)
// concat=0: out[n,64]  = relu(mean_heads(sum)+bias) (layer 2)
__global__ __launch_bounds__(256) void k_agg4(const float* __restrict__ hfull,
                                              const float* __restrict__ bias,
                                              float* __restrict__ out, int concat) {
    int n = blockIdx.x;
    int t = threadIdx.x;
    int head = t >> 6;
    int s = g_rowptr[n], e0 = g_rowptr[n + 1];
    float acc = 0.f;
    for (int j = s; j < e0; j++) {
        int src = g_srcp[j];
        float a = g_alpha[j * 4 + head];
        acc += a * hfull[(size_t)src * 256 + t];
    }
    if (concat) {
        out[(size_t)n * 256 + t] = fmaxf(acc + bias[t], 0.f);
    } else {
        __shared__ float sm[256];
        sm[t] = acc;
        __syncthreads();
        if (t < 64) {
            float v = (sm[t] + sm[t + 64] + sm[t + 128] + sm[t + 192]) * 0.25f + bias[t];
            out[(size_t)n * 64 + t] = fmaxf(v, 0.f);
        }
    }
}

// ---------------- aggregation, 32-feature heads (warp per node) ----------------
__global__ void k_agg1(const float* __restrict__ hf, const float* __restrict__ bias,
                       float* __restrict__ outz) {
    int n = blockIdx.x * 8 + (threadIdx.x >> 5);
    if (n >= NN) return;
    int lane = threadIdx.x & 31;
    int s = g_rowptr[n], e0 = g_rowptr[n + 1];
    float acc = 0.f;
    for (int j = s; j < e0; j++) {
        acc += g_alpha[j] * hf[(size_t)g_srcp[j] * 32 + lane];
    }
    outz[(size_t)n * 32 + lane] = acc + bias[lane];
}

// ---------------- driver ----------------
extern "C" void kernel_launch(void* const* d_in, const int* in_sizes, int n_in,
                              void* d_out, int out_size) {
    const float* x   = (const float*)d_in[0];
    const int*   ei  = (const int*)d_in[1];
    const float* W1  = (const float*)d_in[2];
    const float* a1s = (const float*)d_in[3];
    const float* a1d = (const float*)d_in[4];
    const float* b1  = (const float*)d_in[5];
    const float* W2  = (const float*)d_in[6];
    const float* a2s = (const float*)d_in[7];
    const float* a2d = (const float*)d_in[8];
    const float* b2  = (const float*)d_in[9];
    const float* Wm  = (const float*)d_in[10];
    const float* ams = (const float*)d_in[11];
    const float* amd = (const float*)d_in[12];
    const float* bm  = (const float*)d_in[13];
    const float* Ws  = (const float*)d_in[14];
    const float* ass = (const float*)d_in[15];
    const float* asd = (const float*)d_in[16];
    const float* bs  = (const float*)d_in[17];

    float* out = (float*)d_out;
    float* zm  = out;                 // [N,32]
    float* zs  = out + 1600000;       // [N,32]
    float* aw1 = out + 3200000;       // [ET,4]
    float* aw2 = out + 6600000;       // [ET,4]
    float* awm = out + 10000000;      // [ET,1]
    float* aws = out + 10850000;      // [ET,1]

    const int EB = (ET + 255) / 256;       // edge-parallel blocks
    const int NB8 = (NN + 7) / 8;          // warp-per-node blocks

    // CSR build (per launch, deterministic work)
    k_zero_deg<<<(NN + 255) / 256, 256>>>();
    k_hist<<<EB, 256>>>(ei);
    k_scan<<<1, 1024>>>();
    k_scatter<<<EB, 256>>>(ei);

    // ---- layer 1: 256 -> 4x64, concat ----
    {
        dim3 g(256 / 128, (NN + 127) / 128);
        k_sgemm<<<g, 256>>>(x, W1, g_hfull, NN, 256, 256);
    }
    k_coef4<<<NN, 256>>>(g_hfull, a1s, a1d);
    k_edge4<<<EB, 256>>>();
    k_softmax4<<<NB8, 256>>>(aw1);
    k_agg4<<<NN, 256>>>(g_hfull, b1, g_h1act, 1);

    // ---- layer 2: 256 -> 4x64, mean over heads ----
    {
        dim3 g(256 / 128, (NN + 127) / 128);
        k_sgemm<<<g, 256>>>(g_h1act, W2, g_hfull, NN, 256, 256);
    }
    k_coef4<<<NN, 256>>>(g_hfull, a2s, a2d);
    k_edge4<<<EB, 256>>>();
    k_softmax4<<<NB8, 256>>>(aw2);
    k_agg4<<<NN, 256>>>(g_hfull, b2, g_h2, 0);

    // ---- heads: 64 -> 32, H=1 ----
    k_gemm_small<<<NB8, dim3(32, 8)>>>(g_h2, Wm, g_hm, NN);
    k_gemm_small<<<NB8, dim3(32, 8)>>>(g_h2, Ws, g_hs, NN);

    // mean head
    k_coef1<<<NB8, 256>>>(g_hm, ams, amd);
    k_edge1<<<EB, 256>>>();
    k_softmax1<<<NB8, 256>>>(awm);
    k_agg1<<<NB8, 256>>>(g_hm, bm, zm);

    // log_std head
    k_coef1<<<NB8, 256>>>(g_hs, ass, asd);
    k_edge1<<<EB, 256>>>();
    k_softmax1<<<NB8, 256>>>(aws);
    k_agg1<<<NB8, 256>>>(g_hs, bs, zs);
}

// round 6
// speedup vs baseline: 1.1403x; 1.1403x over previous
#include <cuda_runtime.h>
#include <cstddef>

#define NN 50000
#define EE 800000
#define ET 850000   // EE + NN self loops
#define NEG 0.2f

// ---------------- scratch (static __device__, no allocations) ----------------
__device__ __align__(16) float g_hfull[NN * 256];   // h = act @ W (layer 1/2)
__device__ __align__(16) float g_h1act[NN * 256];   // relu(gat1 out + b1)
__device__ __align__(16) float g_h2[NN * 64];       // relu(mean-head gat2 + b2)
__device__ __align__(16) float g_hm[NN * 32];
__device__ __align__(16) float g_hs[NN * 32];
__device__ __align__(16) float g_esrc[NN * 4];      // also reused as float2 for heads
__device__ __align__(16) float g_edst[NN * 4];
__device__ __align__(16) float g_e[ET * 4];         // logits / exp scratch (float4 or float2 views)
__device__ __align__(16) float g_alpha[ET * 4];     // alpha in CSR order
__device__ int g_deg[NN];
__device__ int g_rowptr[NN + 1];
__device__ int g_cursor[NN];
__device__ int g_perm[ET];   // CSR position -> original edge id
__device__ int g_srcp[ET];   // CSR position -> src node

__device__ __forceinline__ float lrelu(float v) { return v > 0.f ? v : NEG * v; }

// ---------------- CSR build ----------------
__global__ void k_zero_deg() {
    int i = blockIdx.x * blockDim.x + threadIdx.x;
    if (i < NN) g_deg[i] = 0;
}

__global__ void k_hist(const int* __restrict__ ei) {
    int e = blockIdx.x * blockDim.x + threadIdx.x;
    if (e >= ET) return;
    int d = (e < EE) ? ei[EE + e] : (e - EE);
    atomicAdd(&g_deg[d], 1);
}

// single block, 1024 threads, warp-shuffle scan (3 barriers per 1024 chunk)
__global__ void k_scan() {
    __shared__ int wsum[32];
    __shared__ int carry;
    const int tid = threadIdx.x, lane = tid & 31, wid = tid >> 5;
    if (tid == 0) { carry = 0; g_rowptr[0] = 0; }
    __syncthreads();
    for (int base = 0; base < NN; base += 1024) {
        int i = base + tid;
        int v = (i < NN) ? g_deg[i] : 0;
        int x = v;
#pragma unroll
        for (int o = 1; o < 32; o <<= 1) {
            int t = __shfl_up_sync(0xffffffffu, x, o);
            if (lane >= o) x += t;
        }
        if (lane == 31) wsum[wid] = x;
        __syncthreads();
        if (wid == 0) {
            int y = wsum[lane];
#pragma unroll
            for (int o = 1; o < 32; o <<= 1) {
                int t = __shfl_up_sync(0xffffffffu, y, o);
                if (lane >= o) y += t;
            }
            wsum[lane] = y;
        }
        __syncthreads();
        int c = carry;
        int incl = c + (wid ? wsum[wid - 1] : 0) + x;
        if (i < NN) {
            g_rowptr[i + 1] = incl;
            g_cursor[i] = incl - v;
        }
        int total = wsum[31];
        __syncthreads();
        if (tid == 0) carry = c + total;
        __syncthreads();
    }
}

__global__ void k_scatter(const int* __restrict__ ei) {
    int e = blockIdx.x * blockDim.x + threadIdx.x;
    if (e >= ET) return;
    int sN, dN;
    if (e < EE) { sN = ei[e]; dN = ei[EE + e]; }
    else        { sN = dN = e - EE; }
    int pos = atomicAdd(&g_cursor[dN], 1);
    g_perm[pos] = e;
    g_srcp[pos] = sN;
}

// ---------------- SGEMM: C[M,N] = A[M,K] @ B[K,N], 128x128x16, double-buffered ----------------
#define BK 16
__global__ __launch_bounds__(256, 2) void k_sgemm(const float* __restrict__ A,
                                                  const float* __restrict__ B,
                                                  float* __restrict__ C,
                                                  int M, int N, int K) {
    __shared__ float As[BK][132];
    __shared__ float Bs[BK][132];
    const int tid = threadIdx.x;
    const int bm = blockIdx.y * 128, bn = blockIdx.x * 128;
    const int aRow = tid >> 1, aCol = (tid & 1) * 8;   // A tile: 128 rows x 16 k
    const int bRow = tid >> 4, bCol = (tid & 15) * 8;  // B tile: 16 k x 128 n
    const int tx = tid & 15, ty = tid >> 4;
    const int gr = bm + aRow;
    const float* Ap = A + (size_t)gr * K;
    const float* Bp = B + (size_t)bRow * N + bn + bCol;

    float4 pa0, pa1, pb0, pb1;
    if (gr < M) {
        pa0 = *(const float4*)(Ap + aCol);
        pa1 = *(const float4*)(Ap + aCol + 4);
    } else { pa0 = pa1 = make_float4(0.f, 0.f, 0.f, 0.f); }
    pb0 = *(const float4*)(Bp);
    pb1 = *(const float4*)(Bp + 4);

    float acc[8][8] = {};
    const int nt = K / BK;
    for (int kt = 0; kt < nt; kt++) {
        As[aCol + 0][aRow] = pa0.x; As[aCol + 1][aRow] = pa0.y;
        As[aCol + 2][aRow] = pa0.z; As[aCol + 3][aRow] = pa0.w;
        As[aCol + 4][aRow] = pa1.x; As[aCol + 5][aRow] = pa1.y;
        As[aCol + 6][aRow] = pa1.z; As[aCol + 7][aRow] = pa1.w;
        *(float4*)&Bs[bRow][bCol]     = pb0;
        *(float4*)&Bs[bRow][bCol + 4] = pb1;
        __syncthreads();
        if (kt + 1 < nt) {
            int k0 = (kt + 1) * BK;
            if (gr < M) {
                pa0 = *(const float4*)(Ap + k0 + aCol);
                pa1 = *(const float4*)(Ap + k0 + aCol + 4);
            }
            pb0 = *(const float4*)(Bp + (size_t)k0 * N);
            pb1 = *(const float4*)(Bp + (size_t)k0 * N + 4);
        }
#pragma unroll
        for (int k = 0; k < BK; k++) {
            float4 a0 = *(float4*)&As[k][ty * 4];
            float4 a1 = *(float4*)&As[k][64 + ty * 4];
            float4 b0 = *(float4*)&Bs[k][tx * 4];
            float4 b1 = *(float4*)&Bs[k][64 + tx * 4];
            float af[8] = {a0.x, a0.y, a0.z, a0.w, a1.x, a1.y, a1.z, a1.w};
            float bf[8] = {b0.x, b0.y, b0.z, b0.w, b1.x, b1.y, b1.z, b1.w};
#pragma unroll
            for (int i = 0; i < 8; i++)
#pragma unroll
                for (int j = 0; j < 8; j++) acc[i][j] += af[i] * bf[j];
        }
        __syncthreads();
    }
#pragma unroll
    for (int i = 0; i < 8; i++) {
        int gr2 = bm + (i < 4 ? ty * 4 + i : 64 + ty * 4 + (i - 4));
        if (gr2 >= M) continue;
        float* cp = C + (size_t)gr2 * N + bn;
        *(float4*)(cp + tx * 4)      = make_float4(acc[i][0], acc[i][1], acc[i][2], acc[i][3]);
        *(float4*)(cp + 64 + tx * 4) = make_float4(acc[i][4], acc[i][5], acc[i][6], acc[i][7]);
    }
}

// ---------------- fused small GEMM: [M,64] @ Wm,Ws[64,32] -> Cm,Cs[M,32] ----------------
__global__ __launch_bounds__(1024) void k_gemm2(const float* __restrict__ A,
                                                const float* __restrict__ Wm,
                                                const float* __restrict__ Ws,
                                                float* __restrict__ Cm,
                                                float* __restrict__ Cs, int M) {
    __shared__ float Wms[64 * 32];
    __shared__ float Wss[64 * 32];
    int tid = threadIdx.x;
    for (int i = tid; i < 64 * 32; i += 1024) { Wms[i] = Wm[i]; Wss[i] = Ws[i]; }
    __syncthreads();
    int row = blockIdx.x * 32 + (tid >> 5);
    if (row >= M) return;
    int col = tid & 31;
    const float* a = A + (size_t)row * 64;
    float m = 0.f, s = 0.f;
#pragma unroll
    for (int k = 0; k < 64; k++) {
        float av = a[k];
        m += av * Wms[k * 32 + col];
        s += av * Wss[k * 32 + col];
    }
    Cm[(size_t)row * 32 + col] = m;
    Cs[(size_t)row * 32 + col] = s;
}

// ---------------- attention coefficients, 256-feature layers (H=4,C=64) ----------------
__global__ void k_coef4(const float* __restrict__ hfull, const float* __restrict__ as_,
                        const float* __restrict__ ad_) {
    int n = blockIdx.x;
    int t = threadIdx.x;
    float v = hfull[(size_t)n * 256 + t];
    float ps = v * as_[t], pd = v * ad_[t];
#pragma unroll
    for (int o = 16; o > 0; o >>= 1) {
        ps += __shfl_down_sync(0xffffffffu, ps, o);
        pd += __shfl_down_sync(0xffffffffu, pd, o);
    }
    __shared__ float ss[8], sd[8];
    if ((t & 31) == 0) { ss[t >> 5] = ps; sd[t >> 5] = pd; }
    __syncthreads();
    if (t < 4) {
        g_esrc[n * 4 + t] = ss[2 * t] + ss[2 * t + 1];
        g_edst[n * 4 + t] = sd[2 * t] + sd[2 * t + 1];
    }
}

// ---------------- attention coefficients, both 32-feature heads at once ----------------
__global__ void k_coef1x2(const float* __restrict__ hm, const float* __restrict__ hs,
                          const float* __restrict__ ams, const float* __restrict__ amd,
                          const float* __restrict__ ass, const float* __restrict__ asd) {
    int n = blockIdx.x * 8 + (threadIdx.x >> 5);
    if (n >= NN) return;
    int lane = threadIdx.x & 31;
    float vm = hm[(size_t)n * 32 + lane];
    float vs = hs[(size_t)n * 32 + lane];
    float p0 = vm * ams[lane], p1 = vm * amd[lane];
    float p2 = vs * ass[lane], p3 = vs * asd[lane];
#pragma unroll
    for (int o = 16; o > 0; o >>= 1) {
        p0 += __shfl_down_sync(0xffffffffu, p0, o);
        p1 += __shfl_down_sync(0xffffffffu, p1, o);
        p2 += __shfl_down_sync(0xffffffffu, p2, o);
        p3 += __shfl_down_sync(0xffffffffu, p3, o);
    }
    if (lane == 0) {
        ((float2*)g_esrc)[n] = make_float2(p0, p2);
        ((float2*)g_edst)[n] = make_float2(p1, p3);
    }
}

// ---------------- segment softmax (warp per node), H=4, edge logits fused ----------------
__global__ void k_softmax4(float* __restrict__ aw_out) {
    int n = blockIdx.x * 8 + (threadIdx.x >> 5);
    if (n >= NN) return;
    int lane = threadIdx.x & 31;
    int s = g_rowptr[n], t = g_rowptr[n + 1];
    float4 ed = ((const float4*)g_edst)[n];
    float4 mx = make_float4(-1e30f, -1e30f, -1e30f, -1e30f);
    for (int j = s + lane; j < t; j += 32) {
        float4 es = ((const float4*)g_esrc)[g_srcp[j]];
        float4 v;
        v.x = lrelu(es.x + ed.x); v.y = lrelu(es.y + ed.y);
        v.z = lrelu(es.z + ed.z); v.w = lrelu(es.w + ed.w);
        ((float4*)g_e)[j] = v;
        mx.x = fmaxf(mx.x, v.x); mx.y = fmaxf(mx.y, v.y);
        mx.z = fmaxf(mx.z, v.z); mx.w = fmaxf(mx.w, v.w);
    }
#pragma unroll
    for (int o = 16; o > 0; o >>= 1) {
        mx.x = fmaxf(mx.x, __shfl_xor_sync(0xffffffffu, mx.x, o));
        mx.y = fmaxf(mx.y, __shfl_xor_sync(0xffffffffu, mx.y, o));
        mx.z = fmaxf(mx.z, __shfl_xor_sync(0xffffffffu, mx.z, o));
        mx.w = fmaxf(mx.w, __shfl_xor_sync(0xffffffffu, mx.w, o));
    }
    float4 sum = make_float4(0.f, 0.f, 0.f, 0.f);
    for (int j = s + lane; j < t; j += 32) {
        float4 v = ((const float4*)g_e)[j];
        v.x = __expf(v.x - mx.x); v.y = __expf(v.y - mx.y);
        v.z = __expf(v.z - mx.z); v.w = __expf(v.w - mx.w);
        ((float4*)g_e)[j] = v;
        sum.x += v.x; sum.y += v.y; sum.z += v.z; sum.w += v.w;
    }
#pragma unroll
    for (int o = 16; o > 0; o >>= 1) {
        sum.x += __shfl_xor_sync(0xffffffffu, sum.x, o);
        sum.y += __shfl_xor_sync(0xffffffffu, sum.y, o);
        sum.z += __shfl_xor_sync(0xffffffffu, sum.z, o);
        sum.w += __shfl_xor_sync(0xffffffffu, sum.w, o);
    }
    float4 inv;
    inv.x = 1.f / (sum.x + 1e-16f); inv.y = 1.f / (sum.y + 1e-16f);
    inv.z = 1.f / (sum.z + 1e-16f); inv.w = 1.f / (sum.w + 1e-16f);
    for (int j = s + lane; j < t; j += 32) {
        float4 v = ((const float4*)g_e)[j];
        float4 a = make_float4(v.x * inv.x, v.y * inv.y, v.z * inv.z, v.w * inv.w);
        ((float4*)g_alpha)[j] = a;
        ((float4*)aw_out)[g_perm[j]] = a;
    }
}

// ---------------- segment softmax, 2 channels (mean + log_std heads), fused logits ----------------
__global__ void k_softmax2(float* __restrict__ awm, float* __restrict__ aws) {
    int n = blockIdx.x * 8 + (threadIdx.x >> 5);
    if (n >= NN) return;
    int lane = threadIdx.x & 31;
    int s = g_rowptr[n], t = g_rowptr[n + 1];
    float2 ed = ((const float2*)g_edst)[n];
    float mx0 = -1e30f, mx1 = -1e30f;
    for (int j = s + lane; j < t; j += 32) {
        float2 es = ((const float2*)g_esrc)[g_srcp[j]];
        float2 v = make_float2(lrelu(es.x + ed.x), lrelu(es.y + ed.y));
        ((float2*)g_e)[j] = v;
        mx0 = fmaxf(mx0, v.x); mx1 = fmaxf(mx1, v.y);
    }
#pragma unroll
    for (int o = 16; o > 0; o >>= 1) {
        mx0 = fmaxf(mx0, __shfl_xor_sync(0xffffffffu, mx0, o));
        mx1 = fmaxf(mx1, __shfl_xor_sync(0xffffffffu, mx1, o));
    }
    float s0 = 0.f, s1 = 0.f;
    for (int j = s + lane; j < t; j += 32) {
        float2 v = ((const float2*)g_e)[j];
        v.x = __expf(v.x - mx0); v.y = __expf(v.y - mx1);
        ((float2*)g_e)[j] = v;
        s0 += v.x; s1 += v.y;
    }
#pragma unroll
    for (int o = 16; o > 0; o >>= 1) {
        s0 += __shfl_xor_sync(0xffffffffu, s0, o);
        s1 += __shfl_xor_sync(0xffffffffu, s1, o);
    }
    float i0 = 1.f / (s0 + 1e-16f), i1 = 1.f / (s1 + 1e-16f);
    for (int j = s + lane; j < t; j += 32) {
        float2 v = ((const float2*)g_e)[j];
        float2 a = make_float2(v.x * i0, v.y * i1);
        ((float2*)g_alpha)[j] = a;
        int p = g_perm[j];
        awm[p] = a.x;
        aws[p] = a.y;
    }
}

// ---------------- aggregation, 256-feature layers, SMEM-staged edge tiles ----------------
__global__ __launch_bounds__(256) void k_agg4(const float* __restrict__ hfull,
                                              const float* __restrict__ bias,
                                              float* __restrict__ out, int concat) {
    __shared__ int ssrc[64];
    __shared__ float salf[256];
    int n = blockIdx.x;
    int t = threadIdx.x;
    int head = t >> 6;
    int s = g_rowptr[n], e0 = g_rowptr[n + 1];
    float acc = 0.f;
    for (int base = s; base < e0; base += 64) {
        int cnt = min(64, e0 - base);
        __syncthreads();
        if (t < cnt) ssrc[t] = g_srcp[base + t];
        if (t < cnt * 4) salf[t] = g_alpha[(size_t)base * 4 + t];
        __syncthreads();
#pragma unroll 4
        for (int i = 0; i < cnt; i++)
            acc += salf[i * 4 + head] * hfull[(size_t)ssrc[i] * 256 + t];
    }
    if (concat) {
        out[(size_t)n * 256 + t] = fmaxf(acc + bias[t], 0.f);
    } else {
        __shared__ float sm[256];
        sm[t] = acc;
        __syncthreads();
        if (t < 64) {
            float v = (sm[t] + sm[t + 64] + sm[t + 128] + sm[t + 192]) * 0.25f + bias[t];
            out[(size_t)n * 64 + t] = fmaxf(v, 0.f);
        }
    }
}

// ---------------- aggregation, both 32-feature heads (warp per node) ----------------
__global__ void k_agg2(const float* __restrict__ hm, const float* __restrict__ hs,
                       const float* __restrict__ bm, const float* __restrict__ bs,
                       float* __restrict__ zm, float* __restrict__ zs) {
    int n = blockIdx.x * 8 + (threadIdx.x >> 5);
    if (n >= NN) return;
    int lane = threadIdx.x & 31;
    int s = g_rowptr[n], e0 = g_rowptr[n + 1];
    float am = 0.f, as_ = 0.f;
#pragma unroll 4
    for (int j = s; j < e0; j++) {
        int src = g_srcp[j];
        float2 a = ((const float2*)g_alpha)[j];
        am  += a.x * hm[(size_t)src * 32 + lane];
        as_ += a.y * hs[(size_t)src * 32 + lane];
    }
    zm[(size_t)n * 32 + lane] = am + bm[lane];
    zs[(size_t)n * 32 + lane] = as_ + bs[lane];
}

// ---------------- driver ----------------
extern "C" void kernel_launch(void* const* d_in, const int* in_sizes, int n_in,
                              void* d_out, int out_size) {
    const float* x   = (const float*)d_in[0];
    const int*   ei  = (const int*)d_in[1];
    const float* W1  = (const float*)d_in[2];
    const float* a1s = (const float*)d_in[3];
    const float* a1d = (const float*)d_in[4];
    const float* b1  = (const float*)d_in[5];
    const float* W2  = (const float*)d_in[6];
    const float* a2s = (const float*)d_in[7];
    const float* a2d = (const float*)d_in[8];
    const float* b2  = (const float*)d_in[9];
    const float* Wm  = (const float*)d_in[10];
    const float* ams = (const float*)d_in[11];
    const float* amd = (const float*)d_in[12];
    const float* bm  = (const float*)d_in[13];
    const float* Ws  = (const float*)d_in[14];
    const float* ass = (const float*)d_in[15];
    const float* asd = (const float*)d_in[16];
    const float* bs  = (const float*)d_in[17];

    float* out = (float*)d_out;
    float* zm  = out;                 // [N,32]
    float* zs  = out + 1600000;       // [N,32]
    float* aw1 = out + 3200000;       // [ET,4]
    float* aw2 = out + 6600000;       // [ET,4]
    float* awm = out + 10000000;      // [ET,1]
    float* aws = out + 10850000;      // [ET,1]

    const int EB  = (ET + 255) / 256;      // edge-parallel blocks
    const int NB8 = (NN + 7) / 8;          // warp-per-node blocks

    // CSR build
    k_zero_deg<<<(NN + 255) / 256, 256>>>();
    k_hist<<<EB, 256>>>(ei);
    k_scan<<<1, 1024>>>();
    k_scatter<<<EB, 256>>>(ei);

    // ---- layer 1: 256 -> 4x64, concat ----
    {
        dim3 g(2, (NN + 127) / 128);
        k_sgemm<<<g, 256>>>(x, W1, g_hfull, NN, 256, 256);
    }
    k_coef4<<<NN, 256>>>(g_hfull, a1s, a1d);
    k_softmax4<<<NB8, 256>>>(aw1);
    k_agg4<<<NN, 256>>>(g_hfull, b1, g_h1act, 1);

    // ---- layer 2: 256 -> 4x64, mean over heads ----
    {
        dim3 g(2, (NN + 127) / 128);
        k_sgemm<<<g, 256>>>(g_h1act, W2, g_hfull, NN, 256, 256);
    }
    k_coef4<<<NN, 256>>>(g_hfull, a2s, a2d);
    k_softmax4<<<NB8, 256>>>(aw2);
    k_agg4<<<NN, 256>>>(g_hfull, b2, g_h2, 0);

    // ---- heads: 64 -> 32 (both at once), H=1 x 2 channels ----
    k_gemm2<<<(NN + 31) / 32, 1024>>>(g_h2, Wm, Ws, g_hm, g_hs, NN);
    k_coef1x2<<<NB8, 256>>>(g_hm, g_hs, ams, amd, ass, asd);
    k_softmax2<<<NB8, 256>>>(awm, aws);
    k_agg2<<<NB8, 256>>>(g_hm, g_hs, bm, bs, zm, zs);
}

// round 7
// speedup vs baseline: 1.1525x; 1.0108x over previous
#include <cuda_runtime.h>
#include <cstddef>

#define NN 50000
#define EE 800000
#define ET 850000   // EE + NN self loops
#define NEG 0.2f

// ---------------- scratch (static __device__, no allocations) ----------------
__device__ __align__(16) float g_hfull[NN * 256];   // h = act @ W (layer 1/2)
__device__ __align__(16) float g_h1act[NN * 256];   // relu(gat1 out + b1)
__device__ __align__(16) float g_h2[NN * 64];       // relu(mean-head gat2 + b2)
__device__ __align__(16) float g_hm[NN * 32];
__device__ __align__(16) float g_hs[NN * 32];
__device__ __align__(16) float g_esrc[NN * 4];      // reused as float2 for heads
__device__ __align__(16) float g_edst[NN * 4];
__device__ __align__(16) float g_e[ET * 4];         // logits/exp scratch
__device__ __align__(16) float g_alpha[ET * 4];     // alpha in CSR order
__device__ int g_deg[NN];
__device__ int g_rowptr[NN + 1];
__device__ int g_cursor[NN];
__device__ int g_perm[ET];   // CSR position -> original edge id
__device__ int g_srcp[ET];   // CSR position -> src node

__device__ __forceinline__ float lrelu(float v) { return v > 0.f ? v : NEG * v; }

// ---------------- CSR build ----------------
__global__ void k_zero_deg() {
    int i = blockIdx.x * blockDim.x + threadIdx.x;
    if (i < NN) g_deg[i] = 0;
}

__global__ void k_hist(const int* __restrict__ ei) {
    int e = blockIdx.x * blockDim.x + threadIdx.x;
    if (e >= ET) return;
    int d = (e < EE) ? ei[EE + e] : (e - EE);
    atomicAdd(&g_deg[d], 1);
}

// single block, 1024 threads, warp-shuffle scan
__global__ void k_scan() {
    __shared__ int wsum[32];
    __shared__ int carry;
    const int tid = threadIdx.x, lane = tid & 31, wid = tid >> 5;
    if (tid == 0) { carry = 0; g_rowptr[0] = 0; }
    __syncthreads();
    for (int base = 0; base < NN; base += 1024) {
        int i = base + tid;
        int v = (i < NN) ? g_deg[i] : 0;
        int x = v;
#pragma unroll
        for (int o = 1; o < 32; o <<= 1) {
            int t = __shfl_up_sync(0xffffffffu, x, o);
            if (lane >= o) x += t;
        }
        if (lane == 31) wsum[wid] = x;
        __syncthreads();
        if (wid == 0) {
            int y = wsum[lane];
#pragma unroll
            for (int o = 1; o < 32; o <<= 1) {
                int t = __shfl_up_sync(0xffffffffu, y, o);
                if (lane >= o) y += t;
            }
            wsum[lane] = y;
        }
        __syncthreads();
        int c = carry;
        int incl = c + (wid ? wsum[wid - 1] : 0) + x;
        if (i < NN) {
            g_rowptr[i + 1] = incl;
            g_cursor[i] = incl - v;
        }
        int total = wsum[31];
        __syncthreads();
        if (tid == 0) carry = c + total;
        __syncthreads();
    }
}

__global__ void k_scatter(const int* __restrict__ ei) {
    int e = blockIdx.x * blockDim.x + threadIdx.x;
    if (e >= ET) return;
    int sN, dN;
    if (e < EE) { sN = ei[e]; dN = ei[EE + e]; }
    else        { sN = dN = e - EE; }
    int pos = atomicAdd(&g_cursor[dN], 1);
    g_perm[pos] = e;
    g_srcp[pos] = sN;
}

// ---------------- SGEMM: C[M,N] = A[M,K] @ B[K,N], 128x128x16, double-buffered ----------------
// NOTE: no min-blocks clause -> full register budget, zero spill risk.
#define BK 16
__global__ __launch_bounds__(256) void k_sgemm(const float* __restrict__ A,
                                               const float* __restrict__ B,
                                               float* __restrict__ C,
                                               int M, int N, int K) {
    __shared__ float As[BK][132];
    __shared__ float Bs[BK][132];
    const int tid = threadIdx.x;
    const int bm = blockIdx.y * 128, bn = blockIdx.x * 128;
    const int aRow = tid >> 1, aCol = (tid & 1) * 8;   // A tile: 128 rows x 16 k
    const int bRow = tid >> 4, bCol = (tid & 15) * 8;  // B tile: 16 k x 128 n
    const int tx = tid & 15, ty = tid >> 4;
    const int gr = bm + aRow;
    const float* Ap = A + (size_t)gr * K;
    const float* Bp = B + (size_t)bRow * N + bn + bCol;

    float4 pa0, pa1, pb0, pb1;
    if (gr < M) {
        pa0 = *(const float4*)(Ap + aCol);
        pa1 = *(const float4*)(Ap + aCol + 4);
    } else { pa0 = pa1 = make_float4(0.f, 0.f, 0.f, 0.f); }
    pb0 = *(const float4*)(Bp);
    pb1 = *(const float4*)(Bp + 4);

    float acc[8][8] = {};
    const int nt = K / BK;
    for (int kt = 0; kt < nt; kt++) {
        As[aCol + 0][aRow] = pa0.x; As[aCol + 1][aRow] = pa0.y;
        As[aCol + 2][aRow] = pa0.z; As[aCol + 3][aRow] = pa0.w;
        As[aCol + 4][aRow] = pa1.x; As[aCol + 5][aRow] = pa1.y;
        As[aCol + 6][aRow] = pa1.z; As[aCol + 7][aRow] = pa1.w;
        *(float4*)&Bs[bRow][bCol]     = pb0;
        *(float4*)&Bs[bRow][bCol + 4] = pb1;
        __syncthreads();
        if (kt + 1 < nt) {
            int k0 = (kt + 1) * BK;
            if (gr < M) {
                pa0 = *(const float4*)(Ap + k0 + aCol);
                pa1 = *(const float4*)(Ap + k0 + aCol + 4);
            }
            pb0 = *(const float4*)(Bp + (size_t)k0 * N);
            pb1 = *(const float4*)(Bp + (size_t)k0 * N + 4);
        }
#pragma unroll
        for (int k = 0; k < BK; k++) {
            float4 a0 = *(float4*)&As[k][ty * 4];
            float4 a1 = *(float4*)&As[k][64 + ty * 4];
            float4 b0 = *(float4*)&Bs[k][tx * 4];
            float4 b1 = *(float4*)&Bs[k][64 + tx * 4];
            float af[8] = {a0.x, a0.y, a0.z, a0.w, a1.x, a1.y, a1.z, a1.w};
            float bf[8] = {b0.x, b0.y, b0.z, b0.w, b1.x, b1.y, b1.z, b1.w};
#pragma unroll
            for (int i = 0; i < 8; i++)
#pragma unroll
                for (int j = 0; j < 8; j++) acc[i][j] += af[i] * bf[j];
        }
        __syncthreads();
    }
#pragma unroll
    for (int i = 0; i < 8; i++) {
        int gr2 = bm + (i < 4 ? ty * 4 + i : 64 + ty * 4 + (i - 4));
        if (gr2 >= M) continue;
        float* cp = C + (size_t)gr2 * N + bn;
        *(float4*)(cp + tx * 4)      = make_float4(acc[i][0], acc[i][1], acc[i][2], acc[i][3]);
        *(float4*)(cp + 64 + tx * 4) = make_float4(acc[i][4], acc[i][5], acc[i][6], acc[i][7]);
    }
}

// ---------------- fused small GEMM: [M,64] @ Wm,Ws[64,32] -> Cm,Cs[M,32] ----------------
__global__ __launch_bounds__(1024) void k_gemm2(const float* __restrict__ A,
                                                const float* __restrict__ Wm,
                                                const float* __restrict__ Ws,
                                                float* __restrict__ Cm,
                                                float* __restrict__ Cs, int M) {
    __shared__ float Wms[64 * 32];
    __shared__ float Wss[64 * 32];
    int tid = threadIdx.x;
    for (int i = tid; i < 64 * 32; i += 1024) { Wms[i] = Wm[i]; Wss[i] = Ws[i]; }
    __syncthreads();
    int row = blockIdx.x * 32 + (tid >> 5);
    if (row >= M) return;
    int col = tid & 31;
    const float* a = A + (size_t)row * 64;
    float m = 0.f, s = 0.f;
#pragma unroll
    for (int k = 0; k < 64; k++) {
        float av = a[k];
        m += av * Wms[k * 32 + col];
        s += av * Wss[k * 32 + col];
    }
    Cm[(size_t)row * 32 + col] = m;
    Cs[(size_t)row * 32 + col] = s;
}

// ---------------- attention coefficients, warp per node (H=4,C=64) ----------------
__global__ void k_coef4w(const float* __restrict__ hfull, const float* __restrict__ as_,
                         const float* __restrict__ ad_) {
    int n = blockIdx.x * 8 + (threadIdx.x >> 5);
    if (n >= NN) return;
    int lane = threadIdx.x & 31;
    const float4* hp = (const float4*)(hfull + (size_t)n * 256) + lane * 2;
    float4 v0 = hp[0], v1 = hp[1];
    const float4* ap = (const float4*)as_ + lane * 2;
    const float4* dp = (const float4*)ad_ + lane * 2;
    float4 s0 = ap[0], s1 = ap[1];
    float4 d0 = dp[0], d1 = dp[1];
    float ps = v0.x * s0.x + v0.y * s0.y + v0.z * s0.z + v0.w * s0.w
             + v1.x * s1.x + v1.y * s1.y + v1.z * s1.z + v1.w * s1.w;
    float pd = v0.x * d0.x + v0.y * d0.y + v0.z * d0.z + v0.w * d0.w
             + v1.x * d1.x + v1.y * d1.y + v1.z * d1.z + v1.w * d1.w;
    // reduce within octet (8 lanes = 64 features = one head)
#pragma unroll
    for (int o = 4; o > 0; o >>= 1) {
        ps += __shfl_down_sync(0xffffffffu, ps, o);
        pd += __shfl_down_sync(0xffffffffu, pd, o);
    }
    if ((lane & 7) == 0) {
        int h = lane >> 3;
        g_esrc[n * 4 + h] = ps;
        g_edst[n * 4 + h] = pd;
    }
}

// ---------------- attention coefficients, both 32-feature heads at once ----------------
__global__ void k_coef1x2(const float* __restrict__ hm, const float* __restrict__ hs,
                          const float* __restrict__ ams, const float* __restrict__ amd,
                          const float* __restrict__ ass, const float* __restrict__ asd) {
    int n = blockIdx.x * 8 + (threadIdx.x >> 5);
    if (n >= NN) return;
    int lane = threadIdx.x & 31;
    float vm = hm[(size_t)n * 32 + lane];
    float vs = hs[(size_t)n * 32 + lane];
    float p0 = vm * ams[lane], p1 = vm * amd[lane];
    float p2 = vs * ass[lane], p3 = vs * asd[lane];
#pragma unroll
    for (int o = 16; o > 0; o >>= 1) {
        p0 += __shfl_down_sync(0xffffffffu, p0, o);
        p1 += __shfl_down_sync(0xffffffffu, p1, o);
        p2 += __shfl_down_sync(0xffffffffu, p2, o);
        p3 += __shfl_down_sync(0xffffffffu, p3, o);
    }
    if (lane == 0) {
        ((float2*)g_esrc)[n] = make_float2(p0, p2);
        ((float2*)g_edst)[n] = make_float2(p1, p3);
    }
}

// ---------------- segment softmax (warp per node), H=4, edge logits fused ----------------
__global__ void k_softmax4(float* __restrict__ aw_out) {
    int n = blockIdx.x * 8 + (threadIdx.x >> 5);
    if (n >= NN) return;
    int lane = threadIdx.x & 31;
    int s = g_rowptr[n], t = g_rowptr[n + 1];
    float4 ed = ((const float4*)g_edst)[n];
    float4 mx = make_float4(-1e30f, -1e30f, -1e30f, -1e30f);
    for (int j = s + lane; j < t; j += 32) {
        float4 es = ((const float4*)g_esrc)[g_srcp[j]];
        float4 v;
        v.x = lrelu(es.x + ed.x); v.y = lrelu(es.y + ed.y);
        v.z = lrelu(es.z + ed.z); v.w = lrelu(es.w + ed.w);
        ((float4*)g_e)[j] = v;
        mx.x = fmaxf(mx.x, v.x); mx.y = fmaxf(mx.y, v.y);
        mx.z = fmaxf(mx.z, v.z); mx.w = fmaxf(mx.w, v.w);
    }
#pragma unroll
    for (int o = 16; o > 0; o >>= 1) {
        mx.x = fmaxf(mx.x, __shfl_xor_sync(0xffffffffu, mx.x, o));
        mx.y = fmaxf(mx.y, __shfl_xor_sync(0xffffffffu, mx.y, o));
        mx.z = fmaxf(mx.z, __shfl_xor_sync(0xffffffffu, mx.z, o));
        mx.w = fmaxf(mx.w, __shfl_xor_sync(0xffffffffu, mx.w, o));
    }
    float4 sum = make_float4(0.f, 0.f, 0.f, 0.f);
    for (int j = s + lane; j < t; j += 32) {
        float4 v = ((const float4*)g_e)[j];
        v.x = __expf(v.x - mx.x); v.y = __expf(v.y - mx.y);
        v.z = __expf(v.z - mx.z); v.w = __expf(v.w - mx.w);
        ((float4*)g_e)[j] = v;
        sum.x += v.x; sum.y += v.y; sum.z += v.z; sum.w += v.w;
    }
#pragma unroll
    for (int o = 16; o > 0; o >>= 1) {
        sum.x += __shfl_xor_sync(0xffffffffu, sum.x, o);
        sum.y += __shfl_xor_sync(0xffffffffu, sum.y, o);
        sum.z += __shfl_xor_sync(0xffffffffu, sum.z, o);
        sum.w += __shfl_xor_sync(0xffffffffu, sum.w, o);
    }
    float4 inv;
    inv.x = 1.f / (sum.x + 1e-16f); inv.y = 1.f / (sum.y + 1e-16f);
    inv.z = 1.f / (sum.z + 1e-16f); inv.w = 1.f / (sum.w + 1e-16f);
    for (int j = s + lane; j < t; j += 32) {
        float4 v = ((const float4*)g_e)[j];
        float4 a = make_float4(v.x * inv.x, v.y * inv.y, v.z * inv.z, v.w * inv.w);
        ((float4*)g_alpha)[j] = a;
        ((float4*)aw_out)[g_perm[j]] = a;
    }
}

// ---------------- segment softmax, 2 channels (mean + log_std heads) ----------------
__global__ void k_softmax2(float* __restrict__ awm, float* __restrict__ aws) {
    int n = blockIdx.x * 8 + (threadIdx.x >> 5);
    if (n >= NN) return;
    int lane = threadIdx.x & 31;
    int s = g_rowptr[n], t = g_rowptr[n + 1];
    float2 ed = ((const float2*)g_edst)[n];
    float mx0 = -1e30f, mx1 = -1e30f;
    for (int j = s + lane; j < t; j += 32) {
        float2 es = ((const float2*)g_esrc)[g_srcp[j]];
        float2 v = make_float2(lrelu(es.x + ed.x), lrelu(es.y + ed.y));
        ((float2*)g_e)[j] = v;
        mx0 = fmaxf(mx0, v.x); mx1 = fmaxf(mx1, v.y);
    }
#pragma unroll
    for (int o = 16; o > 0; o >>= 1) {
        mx0 = fmaxf(mx0, __shfl_xor_sync(0xffffffffu, mx0, o));
        mx1 = fmaxf(mx1, __shfl_xor_sync(0xffffffffu, mx1, o));
    }
    float s0 = 0.f, s1 = 0.f;
    for (int j = s + lane; j < t; j += 32) {
        float2 v = ((const float2*)g_e)[j];
        v.x = __expf(v.x - mx0); v.y = __expf(v.y - mx1);
        ((float2*)g_e)[j] = v;
        s0 += v.x; s1 += v.y;
    }
#pragma unroll
    for (int o = 16; o > 0; o >>= 1) {
        s0 += __shfl_xor_sync(0xffffffffu, s0, o);
        s1 += __shfl_xor_sync(0xffffffffu, s1, o);
    }
    float i0 = 1.f / (s0 + 1e-16f), i1 = 1.f / (s1 + 1e-16f);
    for (int j = s + lane; j < t; j += 32) {
        float2 v = ((const float2*)g_e)[j];
        float2 a = make_float2(v.x * i0, v.y * i1);
        ((float2*)g_alpha)[j] = a;
        int p = g_perm[j];
        awm[p] = a.x;
        aws[p] = a.y;
    }
}

// ---------------- aggregation, 256-feature layers, SMEM-staged edge tiles ----------------
__global__ __launch_bounds__(256) void k_agg4(const float* __restrict__ hfull,
                                              const float* __restrict__ bias,
                                              float* __restrict__ out, int concat) {
    __shared__ int ssrc[64];
    __shared__ float salf[256];
    int n = blockIdx.x;
    int t = threadIdx.x;
    int head = t >> 6;
    int s = g_rowptr[n], e0 = g_rowptr[n + 1];
    float acc = 0.f;
    for (int base = s; base < e0; base += 64) {
        int cnt = min(64, e0 - base);
        __syncthreads();
        if (t < cnt) ssrc[t] = g_srcp[base + t];
        if (t < cnt * 4) salf[t] = g_alpha[(size_t)base * 4 + t];
        __syncthreads();
#pragma unroll 8
        for (int i = 0; i < cnt; i++)
            acc += salf[i * 4 + head] * hfull[(size_t)ssrc[i] * 256 + t];
    }
    if (concat) {
        out[(size_t)n * 256 + t] = fmaxf(acc + bias[t], 0.f);
    } else {
        __shared__ float sm[256];
        sm[t] = acc;
        __syncthreads();
        if (t < 64) {
            float v = (sm[t] + sm[t + 64] + sm[t + 128] + sm[t + 192]) * 0.25f + bias[t];
            out[(size_t)n * 64 + t] = fmaxf(v, 0.f);
        }
    }
}

// ---------------- aggregation, both 32-feature heads (warp per node) ----------------
__global__ void k_agg2(const float* __restrict__ hm, const float* __restrict__ hs,
                       const float* __restrict__ bm, const float* __restrict__ bs,
                       float* __restrict__ zm, float* __restrict__ zs) {
    int n = blockIdx.x * 8 + (threadIdx.x >> 5);
    if (n >= NN) return;
    int lane = threadIdx.x & 31;
    int s = g_rowptr[n], e0 = g_rowptr[n + 1];
    float am = 0.f, as_ = 0.f;
#pragma unroll 4
    for (int j = s; j < e0; j++) {
        int src = g_srcp[j];
        float2 a = ((const float2*)g_alpha)[j];
        am  += a.x * hm[(size_t)src * 32 + lane];
        as_ += a.y * hs[(size_t)src * 32 + lane];
    }
    zm[(size_t)n * 32 + lane] = am + bm[lane];
    zs[(size_t)n * 32 + lane] = as_ + bs[lane];
}

// ---------------- driver ----------------
extern "C" void kernel_launch(void* const* d_in, const int* in_sizes, int n_in,
                              void* d_out, int out_size) {
    const float* x   = (const float*)d_in[0];
    const int*   ei  = (const int*)d_in[1];
    const float* W1  = (const float*)d_in[2];
    const float* a1s = (const float*)d_in[3];
    const float* a1d = (const float*)d_in[4];
    const float* b1  = (const float*)d_in[5];
    const float* W2  = (const float*)d_in[6];
    const float* a2s = (const float*)d_in[7];
    const float* a2d = (const float*)d_in[8];
    const float* b2  = (const float*)d_in[9];
    const float* Wm  = (const float*)d_in[10];
    const float* ams = (const float*)d_in[11];
    const float* amd = (const float*)d_in[12];
    const float* bm  = (const float*)d_in[13];
    const float* Ws  = (const float*)d_in[14];
    const float* ass = (const float*)d_in[15];
    const float* asd = (const float*)d_in[16];
    const float* bs  = (const float*)d_in[17];

    float* out = (float*)d_out;
    float* zm  = out;                 // [N,32]
    float* zs  = out + 1600000;       // [N,32]
    float* aw1 = out + 3200000;       // [ET,4]
    float* aw2 = out + 6600000;       // [ET,4]
    float* awm = out + 10000000;      // [ET,1]
    float* aws = out + 10850000;      // [ET,1]

    const int EB  = (ET + 255) / 256;
    const int NB8 = (NN + 7) / 8;
    dim3 gg(2, (NN + 127) / 128);

    // launches 0..2: CSR front half (scan needs hist only)
    k_zero_deg<<<(NN + 255) / 256, 256>>>();
    k_hist<<<EB, 256>>>(ei);
    k_scan<<<1, 1024>>>();

    // launch 3: layer-1 SGEMM  <-- lands in the fixed ncu capture slot
    k_sgemm<<<gg, 256>>>(x, W1, g_hfull, NN, 256, 256);

    // CSR back half (needs scan)
    k_scatter<<<EB, 256>>>(ei);

    // ---- layer 1: 256 -> 4x64, concat ----
    k_coef4w<<<NB8, 256>>>(g_hfull, a1s, a1d);
    k_softmax4<<<NB8, 256>>>(aw1);
    k_agg4<<<NN, 256>>>(g_hfull, b1, g_h1act, 1);

    // ---- layer 2: 256 -> 4x64, mean over heads ----
    k_sgemm<<<gg, 256>>>(g_h1act, W2, g_hfull, NN, 256, 256);
    k_coef4w<<<NB8, 256>>>(g_hfull, a2s, a2d);
    k_softmax4<<<NB8, 256>>>(aw2);
    k_agg4<<<NN, 256>>>(g_hfull, b2, g_h2, 0);

    // ---- heads: 64 -> 32 (both at once), H=1 x 2 channels ----
    k_gemm2<<<(NN + 31) / 32, 1024>>>(g_h2, Wm, Ws, g_hm, g_hs, NN);
    k_coef1x2<<<NB8, 256>>>(g_hm, g_hs, ams, amd, ass, asd);
    k_softmax2<<<NB8, 256>>>(awm, aws);
    k_agg2<<<NB8, 256>>>(g_hm, g_hs, bm, bs, zm, zs);
}